// round 1
// baseline (speedup 1.0000x reference)
#include <cuda_runtime.h>
#include <math.h>

#define N_NODES 50000
#define E_MAX   800000

// ---------------- static device scratch (no allocations allowed) ----------------
__device__ float g_tfeat[(size_t)E_MAX * 32];   // 102.4 MB
__device__ float g_q  [N_NODES * 128];
__device__ float g_k  [N_NODES * 128];
__device__ float g_v  [N_NODES * 128];
__device__ float g_qt [N_NODES * 128];
__device__ float g_qbt[N_NODES * 4];
__device__ float g_x1 [N_NODES * 128];
__device__ float g_x2 [N_NODES * 128];
__device__ float g_xc [N_NODES];
__device__ int   g_deg[N_NODES];
__device__ int   g_cur[N_NODES];
__device__ int   g_off[N_NODES + 1];
__device__ int   g_esort[E_MAX];

// ---------------- time encoding: t_feat[e, 2i]=sin(t*r^i), [e,2i+1]=cos ----------------
__global__ void tfeat_kernel(const float* __restrict__ edge_attr, int E) {
    int e = blockIdx.x * blockDim.x + threadIdx.x;
    if (e >= E) return;
    float t = edge_attr[2 * e + 1];
    float buf[32];
#pragma unroll
    for (int i = 0; i < 16; i++) {
        // div_term[i] = exp(-(2i) * ln(10000)/32) = exp(i * -0.575646273)
        float dv = __expf(-0.57564627324851142f * (float)i);
        float a  = t * dv;
        buf[2 * i]     = __sinf(a);
        buf[2 * i + 1] = __cosf(a);
    }
    float4* dst = reinterpret_cast<float4*>(g_tfeat + (size_t)e * 32);
#pragma unroll
    for (int i = 0; i < 8; i++) dst[i] = reinterpret_cast<float4*>(buf)[i];
}

// ---------------- counting sort of edges by dst ----------------
__global__ void zero_kernel() {
    int i = blockIdx.x * blockDim.x + threadIdx.x;
    if (i < N_NODES) { g_deg[i] = 0; g_cur[i] = 0; }
}

__global__ void hist_kernel(const int* __restrict__ ei, int E) {
    int e = blockIdx.x * blockDim.x + threadIdx.x;
    if (e < E) atomicAdd(&g_deg[ei[E + e]], 1);
}

__global__ void scan_kernel(int n) {
    __shared__ int sh[1024];
    int t = threadIdx.x;
    int per = (n + 1023) >> 10;
    int base = t * per;
    int sum = 0;
    for (int j = 0; j < per; j++) { int i = base + j; if (i < n) sum += g_deg[i]; }
    sh[t] = sum;
    __syncthreads();
    for (int o = 1; o < 1024; o <<= 1) {
        int v = (t >= o) ? sh[t - o] : 0;
        __syncthreads();
        sh[t] += v;
        __syncthreads();
    }
    int run = sh[t] - sum;  // exclusive prefix
    for (int j = 0; j < per; j++) {
        int i = base + j;
        if (i < n) { g_off[i] = run; run += g_deg[i]; }
    }
    if (t == 1023) g_off[n] = sh[1023];
}

__global__ void scatter_kernel(const int* __restrict__ ei, int E) {
    int e = blockIdx.x * blockDim.x + threadIdx.x;
    if (e >= E) return;
    int d = ei[E + e];
    int pos = g_off[d] + atomicAdd(&g_cur[d], 1);
    g_esort[pos] = e;
}

// ---------------- fused node linear: q,k,v,qt,qbt ----------------
// q scaled by 1/sqrt(32); qt[i,h,d] = sum_c q'[i,h*32+c] * wt[d, h*32+c]
// qbt[i,h] = sum_c q'[i,h*32+c] * bt[h*32+c]
template <int D>
__global__ __launch_bounds__(128) void node_linear_kernel(
    const float* __restrict__ x_in,
    const float* __restrict__ wq, const float* __restrict__ bq,
    const float* __restrict__ wk, const float* __restrict__ bk,
    const float* __restrict__ wv, const float* __restrict__ bv,
    const float* __restrict__ wt, const float* __restrict__ bt)
{
    const float* __restrict__ x = (D == 64) ? x_in : (const float*)g_x1;
    __shared__ float xs[D * 16];        // transposed: xs[c*16 + n]
    __shared__ float qs[16 * 128];
    __shared__ float wtt[128 * 33];     // wtt[ho*33 + d] = wt[d*128 + ho]
    int col = threadIdx.x;              // 0..127
    int node0 = blockIdx.x * 16;

    for (int idx = col; idx < 16 * D; idx += 128) {
        int n = idx / D, c = idx % D;
        int node = node0 + n;
        xs[c * 16 + n] = (node < N_NODES) ? x[(size_t)node * D + c] : 0.f;
    }
    for (int idx = col; idx < 32 * 128; idx += 128) {
        int d = idx >> 7, ho = idx & 127;
        wtt[ho * 33 + d] = wt[idx];
    }
    __syncthreads();

    float aq[16], ak[16], av[16];
#pragma unroll
    for (int n = 0; n < 16; n++) { aq[n] = 0.f; ak[n] = 0.f; av[n] = 0.f; }

    const float4* xs4 = reinterpret_cast<const float4*>(xs);
    for (int c = 0; c < D; c++) {
        float wqc = wq[c * 128 + col];
        float wkc = wk[c * 128 + col];
        float wvc = wv[c * 128 + col];
        float4 a = xs4[c * 4 + 0], b = xs4[c * 4 + 1];
        float4 cc = xs4[c * 4 + 2], dd = xs4[c * 4 + 3];
        float xv[16] = {a.x, a.y, a.z, a.w, b.x, b.y, b.z, b.w,
                        cc.x, cc.y, cc.z, cc.w, dd.x, dd.y, dd.z, dd.w};
#pragma unroll
        for (int n = 0; n < 16; n++) {
            aq[n] = fmaf(xv[n], wqc, aq[n]);
            ak[n] = fmaf(xv[n], wkc, ak[n]);
            av[n] = fmaf(xv[n], wvc, av[n]);
        }
    }

    float bqc = bq[col], bkc = bk[col], bvc = bv[col];
    const float inv = 0.17677669529663688f;  // 1/sqrt(32)
#pragma unroll
    for (int n = 0; n < 16; n++) {
        int node = node0 + n;
        float qv = (aq[n] + bqc) * inv;
        qs[n * 128 + col] = qv;
        if (node < N_NODES) {
            g_q[node * 128 + col] = qv;
            g_k[node * 128 + col] = ak[n] + bkc;
            g_v[node * 128 + col] = av[n] + bvc;
        }
    }
    __syncthreads();

    int h = col >> 5, d = col & 31;
    float aqt[16];
#pragma unroll
    for (int n = 0; n < 16; n++) aqt[n] = 0.f;
    for (int c = 0; c < 32; c++) {
        float w = wtt[(h * 32 + c) * 33 + d];
#pragma unroll
        for (int n = 0; n < 16; n++)
            aqt[n] = fmaf(qs[n * 128 + h * 32 + c], w, aqt[n]);
    }
#pragma unroll
    for (int n = 0; n < 16; n++) {
        int node = node0 + n;
        if (node < N_NODES) g_qt[node * 128 + col] = aqt[n];
    }

    if (col < 4) {
        for (int n = 0; n < 16; n++) {
            int node = node0 + n;
            if (node >= N_NODES) break;
            float b = 0.f;
            for (int c = 0; c < 32; c++)
                b = fmaf(qs[n * 128 + col * 32 + c], bt[col * 32 + c], b);
            g_qbt[node * 4 + col] = b;
        }
    }
}

// ---------------- per-node online-softmax aggregation (one warp = one node, all 4 heads) ----------------
__global__ __launch_bounds__(256) void edge_agg_kernel(const int* __restrict__ ei, int E, int layer) {
    int lane = threadIdx.x & 31;
    int node = blockIdx.x * 8 + (threadIdx.x >> 5);
    if (node >= N_NODES) return;
    float* __restrict__ xout = (layer == 0) ? g_x1 : g_x2;

    float4 q4  = reinterpret_cast<const float4*>(g_q  + node * 128)[lane];
    float4 qt4 = reinterpret_cast<const float4*>(g_qt + node * 128)[lane];
    int h = lane >> 3;
    float qbt = g_qbt[node * 4 + h];

    int idx = g_off[node], end = g_off[node + 1];
    float m = -INFINITY, s = 0.f;
    float4 acc = make_float4(0.f, 0.f, 0.f, 0.f);

    int e = 0, sn = 0;
    if (idx < end) { e = g_esort[idx]; sn = ei[e]; }
    for (; idx < end; idx++) {
        int ce = e, cs = sn;
        if (idx + 1 < end) { e = g_esort[idx + 1]; sn = ei[e]; }  // prefetch next
        float4 k4 = reinterpret_cast<const float4*>(g_k + (size_t)cs * 128)[lane];
        float4 tf = reinterpret_cast<const float4*>(g_tfeat + (size_t)ce * 32)[lane & 7];
        float4 v4 = reinterpret_cast<const float4*>(g_v + (size_t)cs * 128)[lane];

        float p = q4.x * k4.x;
        p = fmaf(q4.y, k4.y, p); p = fmaf(q4.z, k4.z, p); p = fmaf(q4.w, k4.w, p);
        p = fmaf(qt4.x, tf.x, p); p = fmaf(qt4.y, tf.y, p);
        p = fmaf(qt4.z, tf.z, p); p = fmaf(qt4.w, tf.w, p);
        // reduce within the 8-lane head group
        p += __shfl_xor_sync(0xffffffffu, p, 4);
        p += __shfl_xor_sync(0xffffffffu, p, 2);
        p += __shfl_xor_sync(0xffffffffu, p, 1);
        float alpha = p + qbt;   // 1/sqrt(32) already folded into q

        float mn = fmaxf(m, alpha);
        float c1 = __expf(m - mn);
        float pe = __expf(alpha - mn);
        s = fmaf(s, c1, pe);
        acc.x = fmaf(acc.x, c1, pe * v4.x);
        acc.y = fmaf(acc.y, c1, pe * v4.y);
        acc.z = fmaf(acc.z, c1, pe * v4.z);
        acc.w = fmaf(acc.w, c1, pe * v4.w);
        m = mn;
    }
    float r = 1.f / (s + 1e-16f);
    float4 o = make_float4(fmaxf(acc.x * r, 0.f), fmaxf(acc.y * r, 0.f),
                           fmaxf(acc.z * r, 0.f), fmaxf(acc.w * r, 0.f));
    reinterpret_cast<float4*>(xout + (size_t)node * 128)[lane] = o;
}

// ---------------- final classifier: xc = x2 @ wc ; out = xc[src]+xc[dst]+bc ----------------
__global__ void xc_kernel(const float* __restrict__ wc) {
    int lane = threadIdx.x & 31;
    int node = blockIdx.x * 8 + (threadIdx.x >> 5);
    if (node >= N_NODES) return;
    const float* xr = g_x2 + (size_t)node * 128;
    float p = xr[lane] * wc[lane] + xr[lane + 32] * wc[lane + 32] +
              xr[lane + 64] * wc[lane + 64] + xr[lane + 96] * wc[lane + 96];
#pragma unroll
    for (int o = 16; o; o >>= 1) p += __shfl_xor_sync(0xffffffffu, p, o);
    if (lane == 0) g_xc[node] = p;
}

__global__ void final_kernel(const int* __restrict__ ei, const float* __restrict__ bc,
                             float* __restrict__ out, int E) {
    int e = blockIdx.x * blockDim.x + threadIdx.x;
    if (e >= E) return;
    out[e] = g_xc[ei[e]] + g_xc[ei[E + e]] + bc[0];
}

// ---------------- launch ----------------
extern "C" void kernel_launch(void* const* d_in, const int* in_sizes, int n_in,
                              void* d_out, int out_size) {
    const int*   ei  = (const int*)  d_in[0];
    const float* ea  = (const float*)d_in[1];
    const float* emb = (const float*)d_in[3];
    const float *wq1 = (const float*)d_in[4],  *bq1 = (const float*)d_in[5];
    const float *wk1 = (const float*)d_in[6],  *bk1 = (const float*)d_in[7];
    const float *wv1 = (const float*)d_in[8],  *bv1 = (const float*)d_in[9];
    const float *wt1 = (const float*)d_in[10], *bt1 = (const float*)d_in[11];
    const float *wq2 = (const float*)d_in[12], *bq2 = (const float*)d_in[13];
    const float *wk2 = (const float*)d_in[14], *bk2 = (const float*)d_in[15];
    const float *wv2 = (const float*)d_in[16], *bv2 = (const float*)d_in[17];
    const float *wt2 = (const float*)d_in[18], *bt2 = (const float*)d_in[19];
    const float *wc  = (const float*)d_in[20], *bc  = (const float*)d_in[21];
    float* out = (float*)d_out;

    int E = in_sizes[0] / 2;

    tfeat_kernel<<<(E + 127) / 128, 128>>>(ea, E);
    zero_kernel<<<(N_NODES + 255) / 256, 256>>>();
    hist_kernel<<<(E + 255) / 256, 256>>>(ei, E);
    scan_kernel<<<1, 1024>>>(N_NODES);
    scatter_kernel<<<(E + 255) / 256, 256>>>(ei, E);

    // layer 1 (x = emb[:N], D=64)
    node_linear_kernel<64><<<(N_NODES + 15) / 16, 128>>>(emb, wq1, bq1, wk1, bk1, wv1, bv1, wt1, bt1);
    edge_agg_kernel<<<(N_NODES + 7) / 8, 256>>>(ei, E, 0);

    // layer 2 (x = g_x1, D=128)
    node_linear_kernel<128><<<(N_NODES + 15) / 16, 128>>>(emb /*unused*/, wq2, bq2, wk2, bk2, wv2, bv2, wt2, bt2);
    edge_agg_kernel<<<(N_NODES + 7) / 8, 256>>>(ei, E, 1);

    xc_kernel<<<(N_NODES + 7) / 8, 256>>>(wc);
    final_kernel<<<(E + 255) / 256, 256>>>(ei, bc, out, E);
}